// round 15
// baseline (speedup 1.0000x reference)
#include <cuda_runtime.h>

#define HW 6400
#define C  64
#define NB 4

// Scratch: Q,K,V in [n][token][channel] fp32 (static device arrays — no runtime alloc)
__device__ float g_Q[NB * HW * C];
__device__ float g_K[NB * HW * C];
__device__ float g_V[NB * HW * C];

// ---------- packed f32x2 helpers (sm_103a FFMA2 path) ----------
__device__ __forceinline__ unsigned long long pk2(float lo, float hi) {
    unsigned long long r;
    asm("mov.b64 %0, {%1,%2};" : "=l"(r) : "f"(lo), "f"(hi));
    return r;
}
__device__ __forceinline__ void upk2(unsigned long long v, float& lo, float& hi) {
    asm("mov.b64 {%0,%1}, %2;" : "=f"(lo), "=f"(hi) : "l"(v));
}
#define FMA2(d, a, b) asm("fma.rn.f32x2 %0, %1, %2, %0;" : "+l"(d) : "l"(a), "l"(b))
#define MUL2(d, a)    asm("mul.rn.f32x2 %0, %0, %1;"      : "+l"(d) : "l"(a))

__device__ __forceinline__ float lrelu(float v) { return v >= 0.f ? v : 0.2f * v; }

// ============================================================================
// Stage 1: Q = lrelu(W1 X + b1), K = lrelu(W2 X + b2), V = lrelu(W3 X + b3)
// X: x[n][c][t] (t contiguous).  Output layout: g_*[n][t][o] (o contiguous).
// Block = (batch n, 64-token tile). 256 threads.
// ============================================================================
__global__ __launch_bounds__(256) void conv3_kernel(
    const float* __restrict__ x,
    const float* __restrict__ w1, const float* __restrict__ b1,
    const float* __restrict__ w2, const float* __restrict__ b2,
    const float* __restrict__ w3, const float* __restrict__ b3)
{
    extern __shared__ float sm[];
    float* Xs = sm;            // [64 c][68]  (token tile)
    float* Wt = sm + 64 * 68;  // [3][64 c][65 o] (transposed weights)

    const int n   = blockIdx.y;
    const int t0  = blockIdx.x * 64;
    const int tid = threadIdx.x;

    // Load X tile (coalesced float4)
    const float* xb = x + n * C * HW + t0;
#pragma unroll
    for (int q = 0; q < 4; ++q) {
        int lin = tid + 256 * q;               // 1024 float4 units
        int c = lin >> 4, t4 = (lin & 15) << 2;
        float4 v = *(const float4*)(xb + c * HW + t4);
        *(float4*)&Xs[c * 68 + t4] = v;
    }
    // Load W1/W2/W3 transposed: Wt[c][o] = w[o][c]
#pragma unroll
    for (int q = 0; q < 16; ++q) {
        int lin = tid + 256 * q;               // 4096
        int o = lin >> 6, c = lin & 63;
        Wt[          c * 65 + o] = w1[lin];
        Wt[4160 +    c * 65 + o] = w2[lin];
        Wt[8320 +    c * 65 + o] = w3[lin];
    }
    __syncthreads();

    const int o = tid & 63;        // warp lanes → consecutive o (conflict-free W reads)
    const int g = tid >> 6;        // token group: tt = g*16 + r
    float a1[16], a2[16], a3[16];
#pragma unroll
    for (int r = 0; r < 16; ++r) { a1[r] = 0.f; a2[r] = 0.f; a3[r] = 0.f; }

#pragma unroll 4
    for (int c = 0; c < 64; ++c) {
        float wv1 = Wt[          c * 65 + o];
        float wv2 = Wt[4160 +    c * 65 + o];
        float wv3 = Wt[8320 +    c * 65 + o];
        const float* xr = &Xs[c * 68 + g * 16];
#pragma unroll
        for (int r = 0; r < 16; ++r) {
            float xv = xr[r];                  // broadcast within warp
            a1[r] = fmaf(wv1, xv, a1[r]);
            a2[r] = fmaf(wv2, xv, a2[r]);
            a3[r] = fmaf(wv3, xv, a3[r]);
        }
    }
    float bb1 = b1[o], bb2 = b2[o], bb3 = b3[o];
#pragma unroll
    for (int r = 0; r < 16; ++r) {
        int idx = (n * HW + t0 + g * 16 + r) * C + o;   // coalesced over o
        g_Q[idx] = lrelu(a1[r] + bb1);
        g_K[idx] = lrelu(a2[r] + bb2);
        g_V[idx] = lrelu(a3[r] + bb3);
    }
}

// ============================================================================
// Stage 2: flash attention, fp32, FFMA2-packed.
// Block = (batch n, 64 q-rows). 256 threads, 16x16 thread grid, 4x4 micro-tile.
// smem (floats): Qdup[64][130] | Kt[64 c][66 j] | V[64 j][68 c] | Pdup[64][130]
// ============================================================================
#define QOFF 0
#define KOFF 8320
#define VOFF 12544
#define POFF 16896
#define SMEM_FLOATS 25216   // 100,864 bytes

__global__ __launch_bounds__(256) void attn_kernel(float* __restrict__ out)
{
    extern __shared__ float sm[];
    const int n   = blockIdx.y;
    const int i0  = blockIdx.x * 64;
    const int tid = threadIdx.x;
    const int tx  = tid & 15;    // j / c columns: 4*tx + 0..3
    const int ty  = tid >> 4;    // i rows:        4*ty + 0..3

    // Load Q tile, duplicated per element (feeds packed f32x2 directly)
    const float* Qg = g_Q + (n * HW + i0) * C;
#pragma unroll
    for (int q = 0; q < 4; ++q) {
        int lin = tid + 256 * q;
        int i = lin >> 4, c4 = (lin & 15) << 2;
        float4 v = *(const float4*)(Qg + i * C + c4);
        float* d = &sm[QOFF + i * 130 + 2 * c4];
        d[0] = v.x; d[1] = v.x; d[2] = v.y; d[3] = v.y;
        d[4] = v.z; d[5] = v.z; d[6] = v.w; d[7] = v.w;
    }

    unsigned long long o2[4][2];
    float m_run[4], l_run[4];
#pragma unroll
    for (int r = 0; r < 4; ++r) {
        o2[r][0] = 0ull; o2[r][1] = 0ull;
        m_run[r] = -1e30f; l_run[r] = 0.f;
    }

    const float* Kg = g_K + n * HW * C;
    const float* Vg = g_V + n * HW * C;

    for (int jt = 0; jt < HW / 64; ++jt) {
        __syncthreads();   // previous PV done reading Vs/Psd
        // Load K tile transposed (Kt[c][j]) and V tile (V[j][c])
        const float* kb = Kg + jt * 64 * C;
        const float* vb = Vg + jt * 64 * C;
#pragma unroll
        for (int q = 0; q < 4; ++q) {
            int lin = tid + 256 * q;
            int j = lin >> 4, c4 = (lin & 15) << 2;
            float4 kv = *(const float4*)(kb + j * C + c4);
            sm[KOFF + (c4 + 0) * 66 + j] = kv.x;
            sm[KOFF + (c4 + 1) * 66 + j] = kv.y;
            sm[KOFF + (c4 + 2) * 66 + j] = kv.z;
            sm[KOFF + (c4 + 3) * 66 + j] = kv.w;
            float4 vv = *(const float4*)(vb + j * C + c4);
            *(float4*)&sm[VOFF + j * 68 + c4] = vv;
        }
        __syncthreads();

        // ---- S = Q K^T (packed over j) ----
        unsigned long long s2[4][2];
#pragma unroll
        for (int r = 0; r < 4; ++r) { s2[r][0] = 0ull; s2[r][1] = 0ull; }
#pragma unroll 8
        for (int cc = 0; cc < 64; ++cc) {
            unsigned long long ka  = *(const unsigned long long*)&sm[KOFF + cc * 66 + 4 * tx];
            unsigned long long kb2 = *(const unsigned long long*)&sm[KOFF + cc * 66 + 4 * tx + 2];
#pragma unroll
            for (int r = 0; r < 4; ++r) {
                unsigned long long q2 = *(const unsigned long long*)&sm[QOFF + (4 * ty + r) * 130 + 2 * cc];
                FMA2(s2[r][0], q2, ka);
                FMA2(s2[r][1], q2, kb2);
            }
        }

        // ---- online softmax (row stats reduced over the 16 tx lanes) ----
#pragma unroll
        for (int r = 0; r < 4; ++r) {
            float p0, p1, p2, p3;
            upk2(s2[r][0], p0, p1);
            upk2(s2[r][1], p2, p3);
            float mx = fmaxf(fmaxf(p0, p1), fmaxf(p2, p3));
#pragma unroll
            for (int off = 8; off >= 1; off >>= 1)
                mx = fmaxf(mx, __shfl_xor_sync(0xffffffffu, mx, off));
            float m_new = fmaxf(m_run[r], mx);
            float alpha = __expf(m_run[r] - m_new);
            m_run[r] = m_new;
            p0 = __expf(p0 - m_new);
            p1 = __expf(p1 - m_new);
            p2 = __expf(p2 - m_new);
            p3 = __expf(p3 - m_new);
            float rs = (p0 + p1) + (p2 + p3);
#pragma unroll
            for (int off = 8; off >= 1; off >>= 1)
                rs += __shfl_xor_sync(0xffffffffu, rs, off);
            l_run[r] = l_run[r] * alpha + rs;
            unsigned long long al2 = pk2(alpha, alpha);
            MUL2(o2[r][0], al2);
            MUL2(o2[r][1], al2);
            // store P duplicated for packed PV
            float* pd = &sm[POFF + (4 * ty + r) * 130 + 8 * tx];
            pd[0] = p0; pd[1] = p0; pd[2] = p1; pd[3] = p1;
            pd[4] = p2; pd[5] = p2; pd[6] = p3; pd[7] = p3;
        }
        __syncthreads();

        // ---- O += P V (packed over c) ----
#pragma unroll 8
        for (int j = 0; j < 64; ++j) {
            unsigned long long va  = *(const unsigned long long*)&sm[VOFF + j * 68 + 4 * tx];
            unsigned long long vb2 = *(const unsigned long long*)&sm[VOFF + j * 68 + 4 * tx + 2];
#pragma unroll
            for (int r = 0; r < 4; ++r) {
                unsigned long long pp = *(const unsigned long long*)&sm[POFF + (4 * ty + r) * 130 + 2 * j];
                FMA2(o2[r][0], pp, va);
                FMA2(o2[r][1], pp, vb2);
            }
        }
    }

    // ---- normalize + transpose in smem + coalesced store ([n][c][t] output) ----
    __syncthreads();
#pragma unroll
    for (int r = 0; r < 4; ++r) {
        float inv = 1.f / l_run[r];
        float e0, e1, e2, e3;
        upk2(o2[r][0], e0, e1);
        upk2(o2[r][1], e2, e3);
        int i = 4 * ty + r;
        sm[POFF + (4 * tx + 0) * 65 + i] = e0 * inv;
        sm[POFF + (4 * tx + 1) * 65 + i] = e1 * inv;
        sm[POFF + (4 * tx + 2) * 65 + i] = e2 * inv;
        sm[POFF + (4 * tx + 3) * 65 + i] = e3 * inv;
    }
    __syncthreads();
    float* ob = out + n * C * HW + i0;
#pragma unroll
    for (int q = 0; q < 16; ++q) {
        int lin = tid + 256 * q;
        int c = lin >> 6, ii = lin & 63;
        ob[c * HW + ii] = sm[POFF + c * 65 + ii];
    }
}

// ============================================================================
extern "C" void kernel_launch(void* const* d_in, const int* in_sizes, int n_in,
                              void* d_out, int out_size)
{
    const float* x  = (const float*)d_in[0];
    const float* w1 = (const float*)d_in[1];
    const float* b1 = (const float*)d_in[2];
    const float* w2 = (const float*)d_in[3];
    const float* b2 = (const float*)d_in[4];
    const float* w3 = (const float*)d_in[5];
    const float* b3 = (const float*)d_in[6];
    float* out = (float*)d_out;

    const int conv_smem = (64 * 68 + 3 * 64 * 65) * 4;   // 67,328 B
    const int attn_smem = SMEM_FLOATS * 4;               // 100,864 B
    cudaFuncSetAttribute(conv3_kernel, cudaFuncAttributeMaxDynamicSharedMemorySize, conv_smem);
    cudaFuncSetAttribute(attn_kernel,  cudaFuncAttributeMaxDynamicSharedMemorySize, attn_smem);

    conv3_kernel<<<dim3(HW / 64, NB), 256, conv_smem>>>(x, w1, b1, w2, b2, w3, b3);
    attn_kernel<<<dim3(HW / 64, NB), 256, attn_smem>>>(out);
}

// round 17
// speedup vs baseline: 1.2604x; 1.2604x over previous
#include <cuda_runtime.h>

#define HW 6400
#define C  64
#define NB 4

// Scratch: Q,K,V in [n][token][channel] fp32
__device__ float g_Q[NB * HW * C];
__device__ float g_K[NB * HW * C];
__device__ float g_V[NB * HW * C];

// ---------- packed f32x2 helpers ----------
__device__ __forceinline__ void upk2(unsigned long long v, float& lo, float& hi) {
    asm("mov.b64 {%0,%1}, %2;" : "=f"(lo), "=f"(hi) : "l"(v));
}
#define FMA2(d, a, b) asm("fma.rn.f32x2 %0, %1, %2, %0;" : "+l"(d) : "l"(a), "l"(b))

__device__ __forceinline__ float lrelu(float v) { return v >= 0.f ? v : 0.2f * v; }

// ============================================================================
// Stage 1: Q/K/V = lrelu(Wi X + bi).  x[n][c][t] -> g_*[n][t][o]
// ============================================================================
__global__ __launch_bounds__(256) void conv3_kernel(
    const float* __restrict__ x,
    const float* __restrict__ w1, const float* __restrict__ b1,
    const float* __restrict__ w2, const float* __restrict__ b2,
    const float* __restrict__ w3, const float* __restrict__ b3)
{
    extern __shared__ float sm[];
    float* Xs = sm;            // [64 c][68]
    float* Wt = sm + 64 * 68;  // [3][64 c][65 o]

    const int n   = blockIdx.y;
    const int t0  = blockIdx.x * 64;
    const int tid = threadIdx.x;

    const float* xb = x + n * C * HW + t0;
#pragma unroll
    for (int q = 0; q < 4; ++q) {
        int lin = tid + 256 * q;
        int c = lin >> 4, t4 = (lin & 15) << 2;
        float4 v = *(const float4*)(xb + c * HW + t4);
        *(float4*)&Xs[c * 68 + t4] = v;
    }
#pragma unroll
    for (int q = 0; q < 16; ++q) {
        int lin = tid + 256 * q;
        int o = lin >> 6, c = lin & 63;
        Wt[       c * 65 + o] = w1[lin];
        Wt[4160 + c * 65 + o] = w2[lin];
        Wt[8320 + c * 65 + o] = w3[lin];
    }
    __syncthreads();

    const int o = tid & 63;
    const int g = tid >> 6;
    float a1[16], a2[16], a3[16];
#pragma unroll
    for (int r = 0; r < 16; ++r) { a1[r] = 0.f; a2[r] = 0.f; a3[r] = 0.f; }

#pragma unroll 4
    for (int c = 0; c < 64; ++c) {
        float wv1 = Wt[       c * 65 + o];
        float wv2 = Wt[4160 + c * 65 + o];
        float wv3 = Wt[8320 + c * 65 + o];
        const float* xr = &Xs[c * 68 + g * 16];
#pragma unroll
        for (int r = 0; r < 16; ++r) {
            float xv = xr[r];
            a1[r] = fmaf(wv1, xv, a1[r]);
            a2[r] = fmaf(wv2, xv, a2[r]);
            a3[r] = fmaf(wv3, xv, a3[r]);
        }
    }
    float bb1 = b1[o], bb2 = b2[o], bb3 = b3[o];
#pragma unroll
    for (int r = 0; r < 16; ++r) {
        int idx = (n * HW + t0 + g * 16 + r) * C + o;
        g_Q[idx] = lrelu(a1[r] + bb1);
        g_K[idx] = lrelu(a2[r] + bb2);
        g_V[idx] = lrelu(a3[r] + bb3);
    }
}

// ============================================================================
// Stage 2: flash attention, fp32, reduction-axis-packed FFMA2 (no dup operands)
// Block = 64 q-rows x full KV sweep. 256 threads, tx=tid&15, ty=tid>>4.
//   QK^T : acc[r][s] (f32x2 over c-pairs), rows i=4ty+r, cols j=tx+16s
//   P.V  : acc[r][s] (f32x2 over j-pairs), rows i=4ty+r, cols c=tx+16s
// smem (pitch 66 floats; all hot LDS.64 on even float offsets = 8B aligned,
// strided column reads hit banks 2*tx mod 32 -> conflict-free):
//   Qs[64][66] | Ks[64][66] (aliased by P after QK) | Vt[64][66] | Os[64][66]
// ============================================================================
#define PITCH 66
#define QOFF  0
#define KOFF  4224      // = 64*66
#define VOFF  8448
#define OOFF  12672
#define SMEM_FLOATS 16896   // 67,584 bytes -> 3 blocks/SM

__global__ __launch_bounds__(256, 3) void attn_kernel(float* __restrict__ out)
{
    extern __shared__ float sm[];
    const int n   = blockIdx.y;
    const int i0  = blockIdx.x * 64;
    const int tid = threadIdx.x;
    const int tx  = tid & 15;
    const int ty  = tid >> 4;

    // ---- load Q tile (row-major, pitch 66) + zero Os (8B stores only!) ----
    const float* Qg = g_Q + (n * HW + i0) * C;
#pragma unroll
    for (int q = 0; q < 4; ++q) {
        int lin = tid + 256 * q;
        int i = lin >> 4, c4 = (lin & 15) << 2;
        float4 v = *(const float4*)(Qg + i * C + c4);
        float* d = &sm[QOFF + i * PITCH + c4];
        *(float2*)(d)     = make_float2(v.x, v.y);
        *(float2*)(d + 2) = make_float2(v.z, v.w);
        float* z = &sm[OOFF + i * PITCH + c4];
        *(float2*)(z)     = make_float2(0.f, 0.f);
        *(float2*)(z + 2) = make_float2(0.f, 0.f);
    }

    float m_run[4], l_run[4];
#pragma unroll
    for (int r = 0; r < 4; ++r) { m_run[r] = -1e30f; l_run[r] = 0.f; }

    const float* Kg = g_K + n * HW * C;
    const float* Vg = g_V + n * HW * C;

    const float* qbase = &sm[QOFF + (4 * ty) * PITCH];
    const float* kbase = &sm[KOFF + tx * PITCH];
    const float* vbase = &sm[VOFF + tx * PITCH];
    float*       pbase = &sm[KOFF];      // P aliases Ks
    float*       obase = &sm[OOFF];

    for (int jt = 0; jt < HW / 64; ++jt) {
        __syncthreads();   // (a) previous tile's P/Vt reads complete
        // ---- load K tile row-major, V tile transposed ----
        const float* kb = Kg + jt * 64 * C;
        const float* vb = Vg + jt * 64 * C;
#pragma unroll
        for (int q = 0; q < 4; ++q) {
            int lin = tid + 256 * q;
            int j = lin >> 4, c4 = (lin & 15) << 2;
            float4 kv = *(const float4*)(kb + j * C + c4);
            float* kd = &sm[KOFF + j * PITCH + c4];
            *(float2*)(kd)     = make_float2(kv.x, kv.y);
            *(float2*)(kd + 2) = make_float2(kv.z, kv.w);
            float4 vv = *(const float4*)(vb + j * C + c4);
            sm[VOFF + (c4 + 0) * PITCH + j] = vv.x;
            sm[VOFF + (c4 + 1) * PITCH + j] = vv.y;
            sm[VOFF + (c4 + 2) * PITCH + j] = vv.z;
            sm[VOFF + (c4 + 3) * PITCH + j] = vv.w;
        }
        __syncthreads();   // (b)

        // ---- S = Q K^T, f32x2 packed over c-pairs ----
        unsigned long long acc[4][4];
#pragma unroll
        for (int r = 0; r < 4; ++r)
#pragma unroll
            for (int s = 0; s < 4; ++s) acc[r][s] = 0ull;

#pragma unroll 4
        for (int cp = 0; cp < 32; ++cp) {
            unsigned long long q2[4], k2[4];
#pragma unroll
            for (int r = 0; r < 4; ++r)
                q2[r] = *(const unsigned long long*)(qbase + r * PITCH + 2 * cp);
#pragma unroll
            for (int s = 0; s < 4; ++s)
                k2[s] = *(const unsigned long long*)(kbase + s * 16 * PITCH + 2 * cp);
#pragma unroll
            for (int r = 0; r < 4; ++r)
#pragma unroll
                for (int s = 0; s < 4; ++s)
                    FMA2(acc[r][s], q2[r], k2[s]);
        }

        // ---- online softmax (row stats reduced over the 16 tx lanes) ----
        float pv[4][4], alpha[4];
#pragma unroll
        for (int r = 0; r < 4; ++r) {
#pragma unroll
            for (int s = 0; s < 4; ++s) {
                float lo, hi;
                upk2(acc[r][s], lo, hi);
                pv[r][s] = lo + hi;
            }
            float mx = fmaxf(fmaxf(pv[r][0], pv[r][1]), fmaxf(pv[r][2], pv[r][3]));
#pragma unroll
            for (int off = 8; off >= 1; off >>= 1)
                mx = fmaxf(mx, __shfl_xor_sync(0xffffffffu, mx, off));
            float m_new = fmaxf(m_run[r], mx);
            alpha[r] = __expf(m_run[r] - m_new);
            m_run[r] = m_new;
            float rs = 0.f;
#pragma unroll
            for (int s = 0; s < 4; ++s) {
                pv[r][s] = __expf(pv[r][s] - m_new);
                rs += pv[r][s];
            }
#pragma unroll
            for (int off = 8; off >= 1; off >>= 1)
                rs += __shfl_xor_sync(0xffffffffu, rs, off);
            l_run[r] = l_run[r] * alpha[r] + rs;
        }

        __syncthreads();   // (c) all QK reads of Ks done before P overwrite
#pragma unroll
        for (int r = 0; r < 4; ++r)
#pragma unroll
            for (int s = 0; s < 4; ++s)
                pbase[(4 * ty + r) * PITCH + tx + 16 * s] = pv[r][s];
        __syncthreads();   // (d) P visible

        // ---- O_tile = P V, f32x2 packed over j-pairs ----
        unsigned long long oacc[4][4];
#pragma unroll
        for (int r = 0; r < 4; ++r)
#pragma unroll
            for (int s = 0; s < 4; ++s) oacc[r][s] = 0ull;

#pragma unroll 4
        for (int jp = 0; jp < 32; ++jp) {
            unsigned long long p2[4], v2[4];
#pragma unroll
            for (int r = 0; r < 4; ++r)
                p2[r] = *(const unsigned long long*)(pbase + (4 * ty + r) * PITCH + 2 * jp);
#pragma unroll
            for (int s = 0; s < 4; ++s)
                v2[s] = *(const unsigned long long*)(vbase + s * 16 * PITCH + 2 * jp);
#pragma unroll
            for (int r = 0; r < 4; ++r)
#pragma unroll
                for (int s = 0; s < 4; ++s)
                    FMA2(oacc[r][s], p2[r], v2[s]);
        }

        // ---- merge into running O (each (i,c) owned by exactly one thread) ----
#pragma unroll
        for (int r = 0; r < 4; ++r)
#pragma unroll
            for (int s = 0; s < 4; ++s) {
                float lo, hi;
                upk2(oacc[r][s], lo, hi);
                int idx = (4 * ty + r) * PITCH + tx + 16 * s;
                obase[idx] = obase[idx] * alpha[r] + (lo + hi);
            }
    }

    // ---- normalize + coalesced store to out[n][c][t] ----
    __syncthreads();
    if (tx == 0) {
#pragma unroll
        for (int r = 0; r < 4; ++r)
            sm[QOFF + 4 * ty + r] = 1.f / l_run[r];   // row reciprocals into Qs
    }
    __syncthreads();
    float* ob = out + n * C * HW + i0;
#pragma unroll
    for (int q = 0; q < 16; ++q) {
        int lin = tid + 256 * q;
        int c = lin >> 6, ii = lin & 63;
        ob[c * HW + ii] = sm[OOFF + ii * PITCH + c] * sm[QOFF + ii];
    }
}

// ============================================================================
extern "C" void kernel_launch(void* const* d_in, const int* in_sizes, int n_in,
                              void* d_out, int out_size)
{
    const float* x  = (const float*)d_in[0];
    const float* w1 = (const float*)d_in[1];
    const float* b1 = (const float*)d_in[2];
    const float* w2 = (const float*)d_in[3];
    const float* b2 = (const float*)d_in[4];
    const float* w3 = (const float*)d_in[5];
    const float* b3 = (const float*)d_in[6];
    float* out = (float*)d_out;

    const int conv_smem = (64 * 68 + 3 * 64 * 65) * 4;   // 67,328 B
    const int attn_smem = SMEM_FLOATS * 4;               // 67,584 B
    cudaFuncSetAttribute(conv3_kernel, cudaFuncAttributeMaxDynamicSharedMemorySize, conv_smem);
    cudaFuncSetAttribute(attn_kernel,  cudaFuncAttributeMaxDynamicSharedMemorySize, attn_smem);

    conv3_kernel<<<dim3(HW / 64, NB), 256, conv_smem>>>(x, w1, b1, w2, b2, w3, b3);
    attn_kernel<<<dim3(HW / 64, NB), 256, attn_smem>>>(out);
}